// round 12
// baseline (speedup 1.0000x reference)
#include <cuda_runtime.h>
#include <cuda_bf16.h>
#include <cstdint>

// ---------------------------------------------------------------------------
// Swin block: B=32, H=W=64, DIM=256, HEADS=8, HD=32, WIN=8, SHIFT=4
// ---------------------------------------------------------------------------
#define DIMC    256
#define HEADS   8
#define HD      32
#define SHIFTV  4
#define NTOK    64
#define NWIN    64
#define BATCH   32
#define NWTOT   (BATCH*NWIN)        // 2048
#define ROWS    (BATCH*64*64)       // 131072
#define HIDDEN  1024
#define PARTSZ  (NWTOT*HEADS*NTOK*HD)
#define SCALEQ  0.17677669529663689f

typedef __nv_bfloat16 bf16;

// -------------------------- scratch (device globals) -----------------------
__device__ __align__(16) bf16  g_Xw[ROWS*DIMC];
__device__ __align__(16) bf16  g_QKV[3*PARTSZ];
__device__ __align__(16) bf16  g_O[ROWS*DIMC];
__device__ __align__(16) float g_xmid[ROWS*DIMC];
__device__ __align__(16) bf16  g_X2[ROWS*DIMC];
__device__ __align__(16) bf16  g_H1[ROWS*HIDDEN];
__device__ __align__(16) bf16  g_WqkvT[768*256];
__device__ __align__(16) bf16  g_WpT[256*256];
__device__ __align__(16) bf16  g_W1T[1024*256];
__device__ __align__(16) bf16  g_W2T[256*1024];
__device__ float g_bqkv[768];
__device__ __align__(16) float g_bmask[NWIN*HEADS*64*64];  // fused bias+mask, 8MB

// ------------------------------- PTX helpers -------------------------------
__device__ __forceinline__ void mma16816(float c[4],
    uint32_t a0, uint32_t a1, uint32_t a2, uint32_t a3,
    uint32_t b0, uint32_t b1)
{
    asm volatile(
        "mma.sync.aligned.m16n8k16.row.col.f32.bf16.bf16.f32 "
        "{%0,%1,%2,%3},{%4,%5,%6,%7},{%8,%9},{%0,%1,%2,%3};\n"
        : "+f"(c[0]), "+f"(c[1]), "+f"(c[2]), "+f"(c[3])
        : "r"(a0), "r"(a1), "r"(a2), "r"(a3), "r"(b0), "r"(b1));
}

__device__ __forceinline__ void ldsm_x4(uint32_t& r0, uint32_t& r1,
                                        uint32_t& r2, uint32_t& r3, uint32_t addr)
{
    asm volatile("ldmatrix.sync.aligned.m8n8.x4.shared.b16 {%0,%1,%2,%3},[%4];\n"
        : "=r"(r0), "=r"(r1), "=r"(r2), "=r"(r3) : "r"(addr));
}

__device__ __forceinline__ uint32_t sptr(const void* p) {
    return (uint32_t)__cvta_generic_to_shared(p);
}

__device__ __forceinline__ void cpa16(uint32_t s, const void* g) {
    asm volatile("cp.async.cg.shared.global [%0], [%1], 16;\n" :: "r"(s), "l"(g));
}
__device__ __forceinline__ void cpa_commit() {
    asm volatile("cp.async.commit_group;\n");
}
template<int N>
__device__ __forceinline__ void cpa_wait() {
    asm volatile("cp.async.wait_group %0;\n" :: "n"(N));
}

__device__ __forceinline__ uint32_t pk2(float x, float y) {
    __nv_bfloat162 h = __floats2bfloat162_rn(x, y);
    return *reinterpret_cast<uint32_t*>(&h);
}

__device__ __forceinline__ float gelu_exact(float v) {
    return 0.5f * v * (1.0f + erff(v * 0.7071067811865475f));
}

// -------------------------- prep: weights -> bf16 transposed ---------------
__global__ __launch_bounds__(256) void prep_kernel(
    const float* wq, const float* wk, const float* wv,
    const float* wp, const float* w1, const float* w2,
    const float* bq, const float* bk, const float* bv,
    const float* rel_bias, const int* pos_index, const float* attn_mask)
{
    int i = blockIdx.x * 256 + threadIdx.x;
    if (i < 196608) {                       // WqkvT [768][256]
        int n = i >> 8, k = i & 255;
        int part = n >> 8, nn = n & 255;
        const float* w = (part == 0) ? wq : (part == 1 ? wk : wv);
        g_WqkvT[i] = __float2bfloat16(w[k*256 + nn]);
        return;
    }
    i -= 196608;
    if (i < 65536) {                        // WpT [256][256]
        int n = i >> 8, k = i & 255;
        g_WpT[i] = __float2bfloat16(wp[k*256 + n]);
        return;
    }
    i -= 65536;
    if (i < 262144) {                       // W1T [1024][256]
        int n = i >> 8, k = i & 255;
        g_W1T[i] = __float2bfloat16(w1[k*1024 + n]);
        return;
    }
    i -= 262144;
    if (i < 262144) {                       // W2T [256][1024]
        int n = i >> 10, k = i & 1023;
        g_W2T[i] = __float2bfloat16(w2[k*256 + n]);
        return;
    }
    i -= 262144;
    if (i < 768) {                          // packed qkv bias
        int part = i >> 8, c = i & 255;
        g_bqkv[i] = (part == 0) ? bq[c] : (part == 1 ? bk[c] : bv[c]);
        return;
    }
    i -= 768;
    if (i < NWIN*HEADS*4096) {              // fused bias+mask: [wi][head][i][j]
        int wi = i >> 15, h = (i >> 12) & 7, ij = i & 4095;
        g_bmask[i] = rel_bias[pos_index[ij]*8 + h] + attn_mask[wi*4096 + ij];
    }
}

// -------------------------- LayerNorm (warp per row) -----------------------
__device__ __forceinline__ void ln_row(const float* src, const float* gamma,
                                       const float* beta, bf16* dst, int lane)
{
    float4 v0 = reinterpret_cast<const float4*>(src)[lane];
    float4 v1 = reinterpret_cast<const float4*>(src)[lane + 32];
    float s = v0.x + v0.y + v0.z + v0.w + v1.x + v1.y + v1.z + v1.w;
    float q = v0.x*v0.x + v0.y*v0.y + v0.z*v0.z + v0.w*v0.w
            + v1.x*v1.x + v1.y*v1.y + v1.z*v1.z + v1.w*v1.w;
#pragma unroll
    for (int o = 16; o > 0; o >>= 1) {
        s += __shfl_xor_sync(0xffffffffu, s, o);
        q += __shfl_xor_sync(0xffffffffu, q, o);
    }
    float mu = s * (1.0f/256.0f);
    float var = q * (1.0f/256.0f) - mu*mu;
    float rs = rsqrtf(var + 1e-5f);
    float4 ga = reinterpret_cast<const float4*>(gamma)[lane];
    float4 ba = reinterpret_cast<const float4*>(beta)[lane];
    float4 gb = reinterpret_cast<const float4*>(gamma)[lane + 32];
    float4 bb = reinterpret_cast<const float4*>(beta)[lane + 32];
    __nv_bfloat162 p;
    p = __floats2bfloat162_rn((v0.x-mu)*rs*ga.x + ba.x, (v0.y-mu)*rs*ga.y + ba.y);
    *reinterpret_cast<__nv_bfloat162*>(&dst[lane*4]) = p;
    p = __floats2bfloat162_rn((v0.z-mu)*rs*ga.z + ba.z, (v0.w-mu)*rs*ga.w + ba.w);
    *reinterpret_cast<__nv_bfloat162*>(&dst[lane*4 + 2]) = p;
    p = __floats2bfloat162_rn((v1.x-mu)*rs*gb.x + bb.x, (v1.y-mu)*rs*gb.y + bb.y);
    *reinterpret_cast<__nv_bfloat162*>(&dst[128 + lane*4]) = p;
    p = __floats2bfloat162_rn((v1.z-mu)*rs*gb.z + bb.z, (v1.w-mu)*rs*gb.w + bb.w);
    *reinterpret_cast<__nv_bfloat162*>(&dst[128 + lane*4 + 2]) = p;
}

__global__ __launch_bounds__(256) void ln1_kernel(const float* x,
                                                  const float* gamma, const float* beta)
{
    int r = blockIdx.x * 8 + (threadIdx.x >> 5);
    int lane = threadIdx.x & 31;
    int win = r >> 6, tok = r & 63;
    int b = win >> 6, wi = win & 63;
    int wh = wi >> 3, ww = wi & 7, th = tok >> 3, tw = tok & 7;
    int h0 = ((wh << 3) + th + SHIFTV) & 63;
    int w0 = ((ww << 3) + tw + SHIFTV) & 63;
    size_t src = ((size_t)b << 12) + (h0 << 6) + w0;
    ln_row(x + src*256, gamma, beta, g_Xw + (size_t)r*256, lane);
}

__global__ __launch_bounds__(256) void ln2_kernel(const float* gamma, const float* beta)
{
    int r = blockIdx.x * 8 + (threadIdx.x >> 5);
    int lane = threadIdx.x & 31;
    ln_row(g_xmid + (size_t)r*256, gamma, beta, g_X2 + (size_t)r*256, lane);
}

// -------------------------- GEMM: C = A[M,K] @ BT[N,K]^T + epilogue --------
#define SMA    40    // smem row stride (bf16): 80B, LDSM bank-conflict-free
#define STAGES 4
#define STG_E  (128*SMA)                      // elems per matrix per stage
#define GSMEM  (STAGES*2*STG_E*2)             // bytes of dynamic smem (81920)

__device__ __forceinline__ void epi_store(int mode, int r, int c, float v0, float v1,
                                          const float* bias, const float* xres,
                                          float* outp)
{
    v0 += bias[c];
    v1 += bias[c+1];
    if (mode == 0) {                     // QKV scatter (+scale into Q)
        if (c < 256) { v0 *= SCALEQ; v1 *= SCALEQ; }
        int part = c >> 8, rem = c & 255;
        int head = rem >> 5, d = rem & 31;
        int win = r >> 6, tok = r & 63;
        size_t idx = (size_t)part*PARTSZ
                   + ((((size_t)win*8 + head)*64 + tok)*32 + d);
        *reinterpret_cast<__nv_bfloat162*>(&g_QKV[idx]) = __floats2bfloat162_rn(v0, v1);
    } else if (mode == 1) {              // proj + window-reverse + roll + residual
        int win = r >> 6, tok = r & 63;
        int b = win >> 6, wi = win & 63;
        int wh = wi >> 3, ww = wi & 7, th = tok >> 3, tw = tok & 7;
        int h0 = ((wh << 3) + th + SHIFTV) & 63;
        int w0 = ((ww << 3) + tw + SHIFTV) & 63;
        size_t orow = ((size_t)b << 12) + (h0 << 6) + w0;
        float2 xv = *reinterpret_cast<const float2*>(&xres[orow*256 + c]);
        float2 o; o.x = xv.x + v0; o.y = xv.y + v1;
        *reinterpret_cast<float2*>(&g_xmid[orow*256 + c]) = o;
    } else if (mode == 2) {              // gelu -> bf16
        v0 = gelu_exact(v0);
        v1 = gelu_exact(v1);
        *reinterpret_cast<__nv_bfloat162*>(&g_H1[(size_t)r*1024 + c]) =
            __floats2bfloat162_rn(v0, v1);
    } else {                             // mlp2 + residual -> out (fp32)
        float2 xm = *reinterpret_cast<const float2*>(&g_xmid[(size_t)r*256 + c]);
        float2 o; o.x = xm.x + v0; o.y = xm.y + v1;
        *reinterpret_cast<float2*>(&outp[(size_t)r*256 + c]) = o;
    }
}

__global__ __launch_bounds__(256, 2) void gemm_kernel(int mode, const float* bias_in,
                                                      const float* xres, float* outp)
{
    extern __shared__ __align__(16) bf16 smem[];
    bf16* As = smem;                          // [STAGES][128*SMA]
    bf16* Bs = smem + STAGES*STG_E;           // [STAGES][128*SMA]

    const bf16* A; const bf16* BT; int K; const float* bias;
    if      (mode == 0) { A = g_Xw; BT = g_WqkvT; K = 256;  bias = g_bqkv;  }
    else if (mode == 1) { A = g_O;  BT = g_WpT;   K = 256;  bias = bias_in; }
    else if (mode == 2) { A = g_X2; BT = g_W1T;   K = 256;  bias = bias_in; }
    else                { A = g_H1; BT = g_W2T;   K = 1024; bias = bias_in; }

    const int t = threadIdx.x;
    const int lane = t & 31, warp = t >> 5;
    const int wm = warp & 3, wn = warp >> 2;
    const int g = lane >> 2, tg = lane & 3;
    const int mrow = ((lane >> 3) & 1) * 8 + (lane & 7);
    const int mcol = (lane >> 4) * 8;
    const int m0 = blockIdx.y * 128, n0 = blockIdx.x * 128;
    const int lr = t >> 1, ls = t & 1;

    const bf16* Ag = A  + (size_t)(m0 + lr)*K + ls*16;
    const bf16* Bg = BT + (size_t)(n0 + lr)*K + ls*16;
    const uint32_t sA = sptr(&As[lr*SMA + ls*16]);
    const uint32_t sB = sptr(&Bs[lr*SMA + ls*16]);

    float acc[2][8][4];
#pragma unroll
    for (int mi = 0; mi < 2; ++mi)
#pragma unroll
        for (int ni = 0; ni < 8; ++ni)
#pragma unroll
            for (int j = 0; j < 4; ++j) acc[mi][ni][j] = 0.0f;

    const int nk = K >> 5;

    // prologue: stages 0..STAGES-2
#pragma unroll
    for (int s = 0; s < STAGES-1; ++s) {
        cpa16(sA + s*STG_E*2,      Ag + s*32);
        cpa16(sA + s*STG_E*2 + 16, Ag + s*32 + 8);
        cpa16(sB + s*STG_E*2,      Bg + s*32);
        cpa16(sB + s*STG_E*2 + 16, Bg + s*32 + 8);
        cpa_commit();
    }

    for (int it = 0; it < nk; ++it) {
        cpa_wait<STAGES-2>();
        __syncthreads();

        const int pf = it + STAGES - 1;
        if (pf < nk) {
            const int pb = pf & (STAGES-1);
            cpa16(sA + pb*STG_E*2,      Ag + pf*32);
            cpa16(sA + pb*STG_E*2 + 16, Ag + pf*32 + 8);
            cpa16(sB + pb*STG_E*2,      Bg + pf*32);
            cpa16(sB + pb*STG_E*2 + 16, Bg + pf*32 + 8);
        }
        cpa_commit();

        const int buf = it & (STAGES-1);
        const bf16* Ab = As + buf*STG_E;
        const bf16* Bb = Bs + buf*STG_E;
#pragma unroll
        for (int ks = 0; ks < 2; ++ks) {
            uint32_t af[2][4];
#pragma unroll
            for (int mi = 0; mi < 2; ++mi)
                ldsm_x4(af[mi][0], af[mi][1], af[mi][2], af[mi][3],
                        sptr(&Ab[(wm*32 + mi*16 + mrow)*SMA + ks*16 + mcol]));
#pragma unroll
            for (int nb2 = 0; nb2 < 4; ++nb2) {
                uint32_t b0, b1, b2, b3;
                ldsm_x4(b0, b1, b2, b3,
                        sptr(&Bb[(wn*64 + nb2*16 + mrow)*SMA + ks*16 + mcol]));
                mma16816(acc[0][2*nb2],   af[0][0], af[0][1], af[0][2], af[0][3], b0, b2);
                mma16816(acc[1][2*nb2],   af[1][0], af[1][1], af[1][2], af[1][3], b0, b2);
                mma16816(acc[0][2*nb2+1], af[0][0], af[0][1], af[0][2], af[0][3], b1, b3);
                mma16816(acc[1][2*nb2+1], af[1][0], af[1][1], af[1][2], af[1][3], b1, b3);
            }
        }
    }

#pragma unroll
    for (int mi = 0; mi < 2; ++mi) {
#pragma unroll
        for (int ni = 0; ni < 8; ++ni) {
            int r0 = m0 + wm*32 + mi*16 + g;
            int c0 = n0 + wn*64 + ni*8 + tg*2;
            epi_store(mode, r0,     c0, acc[mi][ni][0], acc[mi][ni][1], bias, xres, outp);
            epi_store(mode, r0 + 8, c0, acc[mi][ni][2], acc[mi][ni][3], bias, xres, outp);
        }
    }
}

// -------------------------- Attention: block per (window, head) ------------
__global__ __launch_bounds__(128) void attn_kernel()
{
    __shared__ __align__(16) bf16 Qs[64*SMA];
    __shared__ __align__(16) bf16 Ks[64*SMA];
    __shared__ __align__(16) bf16 Vst[32*72];     // [d][token]

    const int win = blockIdx.y, head = blockIdx.x;
    const int t = threadIdx.x, lane = t & 31, w = t >> 5;
    const int g = lane >> 2, tg = lane & 3;
    const int mrow = ((lane >> 3) & 1) * 8 + (lane & 7);
    const int mcol = (lane >> 4) * 8;

    const bf16* Qb = g_QKV + ((size_t)(win*8 + head))*64*32;
    const bf16* Kb = Qb + PARTSZ;
    const bf16* Vb = Qb + 2*(size_t)PARTSZ;

#pragma unroll
    for (int ii = 0; ii < 2; ++ii) {
        int idx = t + ii*128;
        int r = idx >> 2, s = idx & 3;
        *reinterpret_cast<uint4*>(&Qs[r*SMA + s*8]) =
            *reinterpret_cast<const uint4*>(Qb + r*32 + s*8);
        *reinterpret_cast<uint4*>(&Ks[r*SMA + s*8]) =
            *reinterpret_cast<const uint4*>(Kb + r*32 + s*8);
        uint4 vv = *reinterpret_cast<const uint4*>(Vb + r*32 + s*8);
        bf16 tmp[8];
        *reinterpret_cast<uint4*>(tmp) = vv;
#pragma unroll
        for (int j2 = 0; j2 < 8; ++j2) Vst[(s*8 + j2)*72 + r] = tmp[j2];
    }
    __syncthreads();

    const int rb = w * 16;

    float sa[8][4];
#pragma unroll
    for (int ni = 0; ni < 8; ++ni)
#pragma unroll
        for (int j = 0; j < 4; ++j) sa[ni][j] = 0.0f;
#pragma unroll
    for (int ks = 0; ks < 2; ++ks) {
        uint32_t a0, a1, a2, a3;
        ldsm_x4(a0, a1, a2, a3, sptr(&Qs[(rb + mrow)*SMA + ks*16 + mcol]));
#pragma unroll
        for (int nb2 = 0; nb2 < 4; ++nb2) {
            uint32_t b0, b1, b2, b3;
            ldsm_x4(b0, b1, b2, b3, sptr(&Ks[(nb2*16 + mrow)*SMA + ks*16 + mcol]));
            mma16816(sa[2*nb2],   a0, a1, a2, a3, b0, b2);
            mma16816(sa[2*nb2+1], a0, a1, a2, a3, b1, b3);
        }
    }

    const int r1 = rb + g, r2 = r1 + 8;
    const float* bm = g_bmask + ((size_t)((win & 63)*8 + head))*4096;
    float mx1 = -1e30f, mx2 = -1e30f;
#pragma unroll
    for (int ni = 0; ni < 8; ++ni) {
        int c = ni*8 + tg*2;
        float2 bv1 = *reinterpret_cast<const float2*>(&bm[r1*64 + c]);
        float2 bv2 = *reinterpret_cast<const float2*>(&bm[r2*64 + c]);
        sa[ni][0] += bv1.x; sa[ni][1] += bv1.y;
        sa[ni][2] += bv2.x; sa[ni][3] += bv2.y;
        mx1 = fmaxf(mx1, fmaxf(sa[ni][0], sa[ni][1]));
        mx2 = fmaxf(mx2, fmaxf(sa[ni][2], sa[ni][3]));
    }
    mx1 = fmaxf(mx1, __shfl_xor_sync(0xffffffffu, mx1, 1));
    mx1 = fmaxf(mx1, __shfl_xor_sync(0xffffffffu, mx1, 2));
    mx2 = fmaxf(mx2, __shfl_xor_sync(0xffffffffu, mx2, 1));
    mx2 = fmaxf(mx2, __shfl_xor_sync(0xffffffffu, mx2, 2));
    float s1 = 0.0f, s2 = 0.0f;
#pragma unroll
    for (int ni = 0; ni < 8; ++ni) {
        sa[ni][0] = __expf(sa[ni][0] - mx1); s1 += sa[ni][0];
        sa[ni][1] = __expf(sa[ni][1] - mx1); s1 += sa[ni][1];
        sa[ni][2] = __expf(sa[ni][2] - mx2); s2 += sa[ni][2];
        sa[ni][3] = __expf(sa[ni][3] - mx2); s2 += sa[ni][3];
    }
    s1 += __shfl_xor_sync(0xffffffffu, s1, 1);
    s1 += __shfl_xor_sync(0xffffffffu, s1, 2);
    s2 += __shfl_xor_sync(0xffffffffu, s2, 1);
    s2 += __shfl_xor_sync(0xffffffffu, s2, 2);
    const float inv1 = 1.0f / s1, inv2 = 1.0f / s2;

    float oa[4][4];
#pragma unroll
    for (int ni = 0; ni < 4; ++ni)
#pragma unroll
        for (int j = 0; j < 4; ++j) oa[ni][j] = 0.0f;
#pragma unroll
    for (int kc = 0; kc < 4; ++kc) {
        uint32_t a0 = pk2(sa[2*kc][0],   sa[2*kc][1]);
        uint32_t a1 = pk2(sa[2*kc][2],   sa[2*kc][3]);
        uint32_t a2 = pk2(sa[2*kc+1][0], sa[2*kc+1][1]);
        uint32_t a3 = pk2(sa[2*kc+1][2], sa[2*kc+1][3]);
#pragma unroll
        for (int nb2 = 0; nb2 < 2; ++nb2) {
            uint32_t b0, b1, b2, b3;
            ldsm_x4(b0, b1, b2, b3, sptr(&Vst[(nb2*16 + mrow)*72 + kc*16 + mcol]));
            mma16816(oa[2*nb2],   a0, a1, a2, a3, b0, b2);
            mma16816(oa[2*nb2+1], a0, a1, a2, a3, b1, b3);
        }
    }
    bf16* Op = g_O + (size_t)win*64*256 + head*32;
#pragma unroll
    for (int ni = 0; ni < 4; ++ni) {
        int d = ni*8 + tg*2;
        *reinterpret_cast<__nv_bfloat162*>(&Op[(size_t)r1*256 + d]) =
            __floats2bfloat162_rn(oa[ni][0]*inv1, oa[ni][1]*inv1);
        *reinterpret_cast<__nv_bfloat162*>(&Op[(size_t)r2*256 + d]) =
            __floats2bfloat162_rn(oa[ni][2]*inv2, oa[ni][3]*inv2);
    }
}

// ---------------------------------------------------------------------------
extern "C" void kernel_launch(void* const* d_in, const int* in_sizes, int n_in,
                              void* d_out, int out_size)
{
    const float* x      = (const float*)d_in[0];
    const float* ln1_g  = (const float*)d_in[1];
    const float* ln1_b  = (const float*)d_in[2];
    const float* wq     = (const float*)d_in[3];
    const float* bq     = (const float*)d_in[4];
    const float* wk     = (const float*)d_in[5];
    const float* bk     = (const float*)d_in[6];
    const float* wv     = (const float*)d_in[7];
    const float* bv     = (const float*)d_in[8];
    const float* wp     = (const float*)d_in[9];
    const float* bp     = (const float*)d_in[10];
    const float* relb   = (const float*)d_in[11];
    const float* ln2_g  = (const float*)d_in[12];
    const float* ln2_b  = (const float*)d_in[13];
    const float* w1     = (const float*)d_in[14];
    const float* b1     = (const float*)d_in[15];
    const float* w2     = (const float*)d_in[16];
    const float* b2     = (const float*)d_in[17];
    const int*   posi   = (const int*)d_in[18];
    const float* amask  = (const float*)d_in[19];
    float* out = (float*)d_out;

    static bool attr_done = false;
    if (!attr_done) {
        cudaFuncSetAttribute(gemm_kernel,
                             cudaFuncAttributeMaxDynamicSharedMemorySize, GSMEM);
        attr_done = true;
    }

    const int prep_elems = 196608 + 65536 + 262144 + 262144 + 768 + NWIN*HEADS*4096;
    prep_kernel<<<(prep_elems + 255)/256, 256>>>(wq, wk, wv, wp, w1, w2,
                                                 bq, bk, bv, relb, posi, amask);
    ln1_kernel<<<ROWS/8, 256>>>(x, ln1_g, ln1_b);
    gemm_kernel<<<dim3(6, ROWS/128), 256, GSMEM>>>(0, nullptr, nullptr, nullptr); // QKV
    attn_kernel<<<dim3(HEADS, NWTOT), 128>>>();
    gemm_kernel<<<dim3(2, ROWS/128), 256, GSMEM>>>(1, bp, x, nullptr);            // proj+res
    ln2_kernel<<<ROWS/8, 256>>>(ln2_g, ln2_b);
    gemm_kernel<<<dim3(8, ROWS/128), 256, GSMEM>>>(2, b1, nullptr, nullptr);      // mlp1+gelu
    gemm_kernel<<<dim3(2, ROWS/128), 256, GSMEM>>>(3, b2, nullptr, out);          // mlp2+res
}

// round 13
// speedup vs baseline: 1.0653x; 1.0653x over previous
#include <cuda_runtime.h>
#include <cuda_bf16.h>
#include <cstdint>

// ---------------------------------------------------------------------------
// Swin block: B=32, H=W=64, DIM=256, HEADS=8, HD=32, WIN=8, SHIFT=4
// ---------------------------------------------------------------------------
#define DIMC    256
#define HEADS   8
#define HD      32
#define SHIFTV  4
#define NTOK    64
#define NWIN    64
#define BATCH   32
#define NWTOT   (BATCH*NWIN)        // 2048
#define ROWS    (BATCH*64*64)       // 131072
#define HIDDEN  1024
#define PARTSZ  (NWTOT*HEADS*NTOK*HD)
#define SCALEQ  0.17677669529663689f

typedef __nv_bfloat16 bf16;

// -------------------------- scratch (device globals) -----------------------
__device__ __align__(16) bf16  g_Xw[ROWS*DIMC];
__device__ __align__(16) bf16  g_QKV[3*PARTSZ];
__device__ __align__(16) bf16  g_O[ROWS*DIMC];
__device__ __align__(16) float g_xmid[ROWS*DIMC];
__device__ __align__(16) bf16  g_X2[ROWS*DIMC];
__device__ __align__(16) bf16  g_H1[ROWS*HIDDEN];
__device__ __align__(16) bf16  g_WqkvT[768*256];
__device__ __align__(16) bf16  g_WpT[256*256];
__device__ __align__(16) bf16  g_W1T[1024*256];
__device__ __align__(16) bf16  g_W2T[256*1024];
__device__ float g_bqkv[768];
__device__ __align__(16) float g_bmask[NWIN*HEADS*64*64];  // fused bias+mask, 8MB

// ------------------------------- PTX helpers -------------------------------
__device__ __forceinline__ void mma16816(float c[4],
    uint32_t a0, uint32_t a1, uint32_t a2, uint32_t a3,
    uint32_t b0, uint32_t b1)
{
    asm volatile(
        "mma.sync.aligned.m16n8k16.row.col.f32.bf16.bf16.f32 "
        "{%0,%1,%2,%3},{%4,%5,%6,%7},{%8,%9},{%0,%1,%2,%3};\n"
        : "+f"(c[0]), "+f"(c[1]), "+f"(c[2]), "+f"(c[3])
        : "r"(a0), "r"(a1), "r"(a2), "r"(a3), "r"(b0), "r"(b1));
}

__device__ __forceinline__ void ldsm_x4(uint32_t& r0, uint32_t& r1,
                                        uint32_t& r2, uint32_t& r3, uint32_t addr)
{
    asm volatile("ldmatrix.sync.aligned.m8n8.x4.shared.b16 {%0,%1,%2,%3},[%4];\n"
        : "=r"(r0), "=r"(r1), "=r"(r2), "=r"(r3) : "r"(addr));
}

__device__ __forceinline__ void ldsm_x4_trans(uint32_t& r0, uint32_t& r1,
                                              uint32_t& r2, uint32_t& r3, uint32_t addr)
{
    asm volatile("ldmatrix.sync.aligned.m8n8.x4.trans.shared.b16 {%0,%1,%2,%3},[%4];\n"
        : "=r"(r0), "=r"(r1), "=r"(r2), "=r"(r3) : "r"(addr));
}

__device__ __forceinline__ uint32_t sptr(const void* p) {
    return (uint32_t)__cvta_generic_to_shared(p);
}

__device__ __forceinline__ void cpa16(uint32_t s, const void* g) {
    asm volatile("cp.async.cg.shared.global [%0], [%1], 16;\n" :: "r"(s), "l"(g));
}
__device__ __forceinline__ void cpa_commit() {
    asm volatile("cp.async.commit_group;\n");
}
template<int N>
__device__ __forceinline__ void cpa_wait() {
    asm volatile("cp.async.wait_group %0;\n" :: "n"(N));
}

__device__ __forceinline__ uint32_t pk2(float x, float y) {
    __nv_bfloat162 h = __floats2bfloat162_rn(x, y);
    return *reinterpret_cast<uint32_t*>(&h);
}

__device__ __forceinline__ float gelu_exact(float v) {
    return 0.5f * v * (1.0f + erff(v * 0.7071067811865475f));
}

// -------------------------- prep: weights -> bf16 transposed ---------------
__global__ __launch_bounds__(256) void prep_kernel(
    const float* wq, const float* wk, const float* wv,
    const float* wp, const float* w1, const float* w2,
    const float* bq, const float* bk, const float* bv,
    const float* rel_bias, const int* pos_index, const float* attn_mask)
{
    int i = blockIdx.x * 256 + threadIdx.x;
    if (i < 196608) {                       // WqkvT [768][256]
        int n = i >> 8, k = i & 255;
        int part = n >> 8, nn = n & 255;
        const float* w = (part == 0) ? wq : (part == 1 ? wk : wv);
        g_WqkvT[i] = __float2bfloat16(w[k*256 + nn]);
        return;
    }
    i -= 196608;
    if (i < 65536) {                        // WpT [256][256]
        int n = i >> 8, k = i & 255;
        g_WpT[i] = __float2bfloat16(wp[k*256 + n]);
        return;
    }
    i -= 65536;
    if (i < 262144) {                       // W1T [1024][256]
        int n = i >> 8, k = i & 255;
        g_W1T[i] = __float2bfloat16(w1[k*1024 + n]);
        return;
    }
    i -= 262144;
    if (i < 262144) {                       // W2T [256][1024]
        int n = i >> 10, k = i & 1023;
        g_W2T[i] = __float2bfloat16(w2[k*256 + n]);
        return;
    }
    i -= 262144;
    if (i < 768) {                          // packed qkv bias
        int part = i >> 8, c = i & 255;
        g_bqkv[i] = (part == 0) ? bq[c] : (part == 1 ? bk[c] : bv[c]);
        return;
    }
    i -= 768;
    if (i < NWIN*HEADS*4096) {              // fused bias+mask: [wi][head][i][j]
        int wi = i >> 15, h = (i >> 12) & 7, ij = i & 4095;
        g_bmask[i] = rel_bias[pos_index[ij]*8 + h] + attn_mask[wi*4096 + ij];
    }
}

// -------------------------- LayerNorm (warp per row) -----------------------
__device__ __forceinline__ void ln_row(const float* src, const float* gamma,
                                       const float* beta, bf16* dst, int lane)
{
    float4 v0 = reinterpret_cast<const float4*>(src)[lane];
    float4 v1 = reinterpret_cast<const float4*>(src)[lane + 32];
    float s = v0.x + v0.y + v0.z + v0.w + v1.x + v1.y + v1.z + v1.w;
    float q = v0.x*v0.x + v0.y*v0.y + v0.z*v0.z + v0.w*v0.w
            + v1.x*v1.x + v1.y*v1.y + v1.z*v1.z + v1.w*v1.w;
#pragma unroll
    for (int o = 16; o > 0; o >>= 1) {
        s += __shfl_xor_sync(0xffffffffu, s, o);
        q += __shfl_xor_sync(0xffffffffu, q, o);
    }
    float mu = s * (1.0f/256.0f);
    float var = q * (1.0f/256.0f) - mu*mu;
    float rs = rsqrtf(var + 1e-5f);
    float4 ga = reinterpret_cast<const float4*>(gamma)[lane];
    float4 ba = reinterpret_cast<const float4*>(beta)[lane];
    float4 gb = reinterpret_cast<const float4*>(gamma)[lane + 32];
    float4 bb = reinterpret_cast<const float4*>(beta)[lane + 32];
    __nv_bfloat162 p;
    p = __floats2bfloat162_rn((v0.x-mu)*rs*ga.x + ba.x, (v0.y-mu)*rs*ga.y + ba.y);
    *reinterpret_cast<__nv_bfloat162*>(&dst[lane*4]) = p;
    p = __floats2bfloat162_rn((v0.z-mu)*rs*ga.z + ba.z, (v0.w-mu)*rs*ga.w + ba.w);
    *reinterpret_cast<__nv_bfloat162*>(&dst[lane*4 + 2]) = p;
    p = __floats2bfloat162_rn((v1.x-mu)*rs*gb.x + bb.x, (v1.y-mu)*rs*gb.y + bb.y);
    *reinterpret_cast<__nv_bfloat162*>(&dst[128 + lane*4]) = p;
    p = __floats2bfloat162_rn((v1.z-mu)*rs*gb.z + bb.z, (v1.w-mu)*rs*gb.w + bb.w);
    *reinterpret_cast<__nv_bfloat162*>(&dst[128 + lane*4 + 2]) = p;
}

__global__ __launch_bounds__(256) void ln1_kernel(const float* x,
                                                  const float* gamma, const float* beta)
{
    int r = blockIdx.x * 8 + (threadIdx.x >> 5);
    int lane = threadIdx.x & 31;
    int win = r >> 6, tok = r & 63;
    int b = win >> 6, wi = win & 63;
    int wh = wi >> 3, ww = wi & 7, th = tok >> 3, tw = tok & 7;
    int h0 = ((wh << 3) + th + SHIFTV) & 63;
    int w0 = ((ww << 3) + tw + SHIFTV) & 63;
    size_t src = ((size_t)b << 12) + (h0 << 6) + w0;
    ln_row(x + src*256, gamma, beta, g_Xw + (size_t)r*256, lane);
}

// -------------------------- GEMM: C = A[M,K] @ BT[N,K]^T + epilogue --------
#define SMA    40    // smem row stride (bf16): 80B, LDSM bank-conflict-free
#define STAGES 4
#define STG_E  (128*SMA)                      // elems per matrix per stage
#define GSMEM  (STAGES*2*STG_E*2)             // bytes of dynamic smem (81920)

__device__ __forceinline__ void epi_store(int mode, int r, int c, float v0, float v1,
                                          const float* bias, const float* xres,
                                          float* outp)
{
    v0 += bias[c];
    v1 += bias[c+1];
    if (mode == 0) {                     // QKV scatter (+scale into Q)
        if (c < 256) { v0 *= SCALEQ; v1 *= SCALEQ; }
        int part = c >> 8, rem = c & 255;
        int head = rem >> 5, d = rem & 31;
        int win = r >> 6, tok = r & 63;
        size_t idx = (size_t)part*PARTSZ
                   + ((((size_t)win*8 + head)*64 + tok)*32 + d);
        *reinterpret_cast<__nv_bfloat162*>(&g_QKV[idx]) = __floats2bfloat162_rn(v0, v1);
    } else if (mode == 2) {              // gelu -> bf16
        v0 = gelu_exact(v0);
        v1 = gelu_exact(v1);
        *reinterpret_cast<__nv_bfloat162*>(&g_H1[(size_t)r*1024 + c]) =
            __floats2bfloat162_rn(v0, v1);
    } else {                             // mlp2 + residual -> out (fp32)
        float2 xm = *reinterpret_cast<const float2*>(&g_xmid[(size_t)r*256 + c]);
        float2 o; o.x = xm.x + v0; o.y = xm.y + v1;
        *reinterpret_cast<float2*>(&outp[(size_t)r*256 + c]) = o;
    }
}

__global__ __launch_bounds__(256, 2) void gemm_kernel(int mode, const float* bias_in,
                                                      const float* xres, float* outp)
{
    extern __shared__ __align__(16) bf16 smem[];
    bf16* As = smem;                          // [STAGES][128*SMA]
    bf16* Bs = smem + STAGES*STG_E;           // [STAGES][128*SMA]

    const bf16* A; const bf16* BT; int K; const float* bias;
    if      (mode == 0) { A = g_Xw; BT = g_WqkvT; K = 256;  bias = g_bqkv;  }
    else if (mode == 2) { A = g_X2; BT = g_W1T;   K = 256;  bias = bias_in; }
    else                { A = g_H1; BT = g_W2T;   K = 1024; bias = bias_in; }

    const int t = threadIdx.x;
    const int lane = t & 31, warp = t >> 5;
    const int wm = warp & 3, wn = warp >> 2;
    const int g = lane >> 2, tg = lane & 3;
    const int mrow = ((lane >> 3) & 1) * 8 + (lane & 7);
    const int mcol = (lane >> 4) * 8;
    const int m0 = blockIdx.y * 128, n0 = blockIdx.x * 128;
    const int lr = t >> 1, ls = t & 1;

    const bf16* Ag = A  + (size_t)(m0 + lr)*K + ls*16;
    const bf16* Bg = BT + (size_t)(n0 + lr)*K + ls*16;
    const uint32_t sA = sptr(&As[lr*SMA + ls*16]);
    const uint32_t sB = sptr(&Bs[lr*SMA + ls*16]);

    float acc[2][8][4];
#pragma unroll
    for (int mi = 0; mi < 2; ++mi)
#pragma unroll
        for (int ni = 0; ni < 8; ++ni)
#pragma unroll
            for (int j = 0; j < 4; ++j) acc[mi][ni][j] = 0.0f;

    const int nk = K >> 5;

#pragma unroll
    for (int s = 0; s < STAGES-1; ++s) {
        cpa16(sA + s*STG_E*2,      Ag + s*32);
        cpa16(sA + s*STG_E*2 + 16, Ag + s*32 + 8);
        cpa16(sB + s*STG_E*2,      Bg + s*32);
        cpa16(sB + s*STG_E*2 + 16, Bg + s*32 + 8);
        cpa_commit();
    }

    for (int it = 0; it < nk; ++it) {
        cpa_wait<STAGES-2>();
        __syncthreads();

        const int pf = it + STAGES - 1;
        if (pf < nk) {
            const int pb = pf & (STAGES-1);
            cpa16(sA + pb*STG_E*2,      Ag + pf*32);
            cpa16(sA + pb*STG_E*2 + 16, Ag + pf*32 + 8);
            cpa16(sB + pb*STG_E*2,      Bg + pf*32);
            cpa16(sB + pb*STG_E*2 + 16, Bg + pf*32 + 8);
        }
        cpa_commit();

        const int buf = it & (STAGES-1);
        const bf16* Ab = As + buf*STG_E;
        const bf16* Bb = Bs + buf*STG_E;
#pragma unroll
        for (int ks = 0; ks < 2; ++ks) {
            uint32_t af[2][4];
#pragma unroll
            for (int mi = 0; mi < 2; ++mi)
                ldsm_x4(af[mi][0], af[mi][1], af[mi][2], af[mi][3],
                        sptr(&Ab[(wm*32 + mi*16 + mrow)*SMA + ks*16 + mcol]));
#pragma unroll
            for (int nb2 = 0; nb2 < 4; ++nb2) {
                uint32_t b0, b1, b2, b3;
                ldsm_x4(b0, b1, b2, b3,
                        sptr(&Bb[(wn*64 + nb2*16 + mrow)*SMA + ks*16 + mcol]));
                mma16816(acc[0][2*nb2],   af[0][0], af[0][1], af[0][2], af[0][3], b0, b2);
                mma16816(acc[1][2*nb2],   af[1][0], af[1][1], af[1][2], af[1][3], b0, b2);
                mma16816(acc[0][2*nb2+1], af[0][0], af[0][1], af[0][2], af[0][3], b1, b3);
                mma16816(acc[1][2*nb2+1], af[1][0], af[1][1], af[1][2], af[1][3], b1, b3);
            }
        }
    }

#pragma unroll
    for (int mi = 0; mi < 2; ++mi) {
#pragma unroll
        for (int ni = 0; ni < 8; ++ni) {
            int r0 = m0 + wm*32 + mi*16 + g;
            int c0 = n0 + wn*64 + ni*8 + tg*2;
            epi_store(mode, r0,     c0, acc[mi][ni][0], acc[mi][ni][1], bias, xres, outp);
            epi_store(mode, r0 + 8, c0, acc[mi][ni][2], acc[mi][ni][3], bias, xres, outp);
        }
    }
}

// ----------- proj GEMM (128x256 full-row tile) + residual + fused LN2 ------
// A = g_O [M,256], B = WpT [256,256]. 512 threads, 16 warps (wm 0..3, wn 0..3).
// Epilogue: o = acc + bp + x  -> g_xmid ; LN2(o) -> g_X2 (bf16).
#define P_ASTG (128*SMA)
#define P_BSTG (256*SMA)
#define PSMEM  (STAGES*(128+256)*SMA*2)      // 122880 bytes

__global__ __launch_bounds__(512, 1) void proj_ln2_kernel(
    const float* bp, const float* xres, const float* lg, const float* lb)
{
    extern __shared__ __align__(16) bf16 smem[];
    bf16* As = smem;                          // [STAGES][128*SMA]
    bf16* Bs = smem + STAGES*P_ASTG;          // [STAGES][256*SMA]

    const int t = threadIdx.x;
    const int lane = t & 31, warp = t >> 5;
    const int wm = warp & 3, wn = warp >> 2;
    const int g = lane >> 2, tg = lane & 3;
    const int mrow = ((lane >> 3) & 1) * 8 + (lane & 7);
    const int mcol = (lane >> 4) * 8;
    const int m0 = blockIdx.y * 128;
    const int K = 256;

    // loaders: B rows 0..255 (all threads), A rows 0..127 (t<256)
    const int lrB = t >> 1, lsB = t & 1;
    const bf16* Bg = g_WpT + (size_t)lrB*K + lsB*16;
    const uint32_t sB = sptr(&Bs[lrB*SMA + lsB*16]);
    const int lrA = (t < 256) ? (t >> 1) : 0;
    const int lsA = t & 1;
    const bf16* Ag = g_O + (size_t)(m0 + lrA)*K + lsA*16;
    const uint32_t sA = sptr(&As[lrA*SMA + lsA*16]);

    float acc[2][8][4];
#pragma unroll
    for (int mi = 0; mi < 2; ++mi)
#pragma unroll
        for (int ni = 0; ni < 8; ++ni)
#pragma unroll
            for (int j = 0; j < 4; ++j) acc[mi][ni][j] = 0.0f;

    const int nk = K >> 5;   // 8

#pragma unroll
    for (int s = 0; s < STAGES-1; ++s) {
        if (t < 256) {
            cpa16(sA + s*P_ASTG*2,      Ag + s*32);
            cpa16(sA + s*P_ASTG*2 + 16, Ag + s*32 + 8);
        }
        cpa16(sB + s*P_BSTG*2,      Bg + s*32);
        cpa16(sB + s*P_BSTG*2 + 16, Bg + s*32 + 8);
        cpa_commit();
    }

    for (int it = 0; it < nk; ++it) {
        cpa_wait<STAGES-2>();
        __syncthreads();

        const int pf = it + STAGES - 1;
        if (pf < nk) {
            const int pb = pf & (STAGES-1);
            if (t < 256) {
                cpa16(sA + pb*P_ASTG*2,      Ag + pf*32);
                cpa16(sA + pb*P_ASTG*2 + 16, Ag + pf*32 + 8);
            }
            cpa16(sB + pb*P_BSTG*2,      Bg + pf*32);
            cpa16(sB + pb*P_BSTG*2 + 16, Bg + pf*32 + 8);
        }
        cpa_commit();

        const int buf = it & (STAGES-1);
        const bf16* Ab = As + buf*P_ASTG;
        const bf16* Bb = Bs + buf*P_BSTG;
#pragma unroll
        for (int ks = 0; ks < 2; ++ks) {
            uint32_t af[2][4];
#pragma unroll
            for (int mi = 0; mi < 2; ++mi)
                ldsm_x4(af[mi][0], af[mi][1], af[mi][2], af[mi][3],
                        sptr(&Ab[(wm*32 + mi*16 + mrow)*SMA + ks*16 + mcol]));
#pragma unroll
            for (int nb2 = 0; nb2 < 4; ++nb2) {
                uint32_t b0, b1, b2, b3;
                ldsm_x4(b0, b1, b2, b3,
                        sptr(&Bb[(wn*64 + nb2*16 + mrow)*SMA + ks*16 + mcol]));
                mma16816(acc[0][2*nb2],   af[0][0], af[0][1], af[0][2], af[0][3], b0, b2);
                mma16816(acc[1][2*nb2],   af[1][0], af[1][1], af[1][2], af[1][3], b0, b2);
                mma16816(acc[0][2*nb2+1], af[0][0], af[0][1], af[0][2], af[0][3], b1, b3);
                mma16816(acc[1][2*nb2+1], af[1][0], af[1][1], af[1][2], af[1][3], b1, b3);
            }
        }
    }

    __syncthreads();   // smem reuse for LN reduction

    // ---- epilogue: bias + residual -> g_xmid; LN2 stats ----
    float2* part = reinterpret_cast<float2*>(smem);          // [128][16]
    float*  muS  = reinterpret_cast<float*>(part + 128*16);  // [128]
    float*  rsS  = muS + 128;                                // [128]

    size_t orw[2][2];
    float sums[2][2], sqs[2][2];
#pragma unroll
    for (int mi = 0; mi < 2; ++mi) {
#pragma unroll
        for (int hf = 0; hf < 2; ++hf) {
            int R = m0 + wm*32 + mi*16 + g + hf*8;
            int win = R >> 6, tok = R & 63;
            int b = win >> 6, wi = win & 63;
            int wh = wi >> 3, ww = wi & 7, th = tok >> 3, tw = tok & 7;
            int h0 = ((wh << 3) + th + SHIFTV) & 63;
            int w0 = ((ww << 3) + tw + SHIFTV) & 63;
            orw[mi][hf] = ((size_t)b << 12) + (h0 << 6) + w0;
            sums[mi][hf] = 0.0f; sqs[mi][hf] = 0.0f;
        }
    }
#pragma unroll
    for (int mi = 0; mi < 2; ++mi) {
#pragma unroll
        for (int ni = 0; ni < 8; ++ni) {
            int c = wn*64 + ni*8 + tg*2;
            float b0 = bp[c], b1 = bp[c+1];
#pragma unroll
            for (int hf = 0; hf < 2; ++hf) {
                float2 xv = *reinterpret_cast<const float2*>(&xres[orw[mi][hf]*256 + c]);
                float v0 = acc[mi][ni][2*hf]   + b0 + xv.x;
                float v1 = acc[mi][ni][2*hf+1] + b1 + xv.y;
                acc[mi][ni][2*hf]   = v0;
                acc[mi][ni][2*hf+1] = v1;
                float2 o; o.x = v0; o.y = v1;
                *reinterpret_cast<float2*>(&g_xmid[orw[mi][hf]*256 + c]) = o;
                sums[mi][hf] += v0 + v1;
                sqs[mi][hf]  += v0*v0 + v1*v1;
            }
        }
    }
#pragma unroll
    for (int mi = 0; mi < 2; ++mi)
#pragma unroll
        for (int hf = 0; hf < 2; ++hf) {
            int prow = wm*32 + mi*16 + g + hf*8;
            part[prow*16 + wn*4 + tg] = make_float2(sums[mi][hf], sqs[mi][hf]);
        }
    __syncthreads();
    if (t < 128) {
        float s = 0.0f, q = 0.0f;
#pragma unroll
        for (int i = 0; i < 16; ++i) {
            float2 p = part[t*16 + i];
            s += p.x; q += p.y;
        }
        float mu = s * (1.0f/256.0f);
        float var = q * (1.0f/256.0f) - mu*mu;
        muS[t] = mu;
        rsS[t] = rsqrtf(var + 1e-5f);
    }
    __syncthreads();
#pragma unroll
    for (int mi = 0; mi < 2; ++mi) {
#pragma unroll
        for (int hf = 0; hf < 2; ++hf) {
            int prow = wm*32 + mi*16 + g + hf*8;
            float mu = muS[prow], rs = rsS[prow];
            bf16* dst = g_X2 + orw[mi][hf]*256;
#pragma unroll
            for (int ni = 0; ni < 8; ++ni) {
                int c = wn*64 + ni*8 + tg*2;
                float v0 = (acc[mi][ni][2*hf]   - mu)*rs*lg[c]   + lb[c];
                float v1 = (acc[mi][ni][2*hf+1] - mu)*rs*lg[c+1] + lb[c+1];
                *reinterpret_cast<__nv_bfloat162*>(&dst[c]) = __floats2bfloat162_rn(v0, v1);
            }
        }
    }
}

// -------------------------- Attention: block per (window, head) ------------
__global__ __launch_bounds__(128) void attn_kernel()
{
    __shared__ __align__(16) bf16 Qs[64*SMA];
    __shared__ __align__(16) bf16 Ks[64*SMA];
    __shared__ __align__(16) bf16 Vs[64*SMA];     // [token][d], rows like K

    const int win = blockIdx.y, head = blockIdx.x;
    const int t = threadIdx.x, lane = t & 31, w = t >> 5;
    const int g = lane >> 2, tg = lane & 3;
    const int mrow = ((lane >> 3) & 1) * 8 + (lane & 7);
    const int mcol = (lane >> 4) * 8;

    const bf16* Qb = g_QKV + ((size_t)(win*8 + head))*64*32;
    const bf16* Kb = Qb + PARTSZ;
    const bf16* Vb = Qb + 2*(size_t)PARTSZ;

#pragma unroll
    for (int ii = 0; ii < 2; ++ii) {
        int idx = t + ii*128;
        int r = idx >> 2, s = idx & 3;
        *reinterpret_cast<uint4*>(&Qs[r*SMA + s*8]) =
            *reinterpret_cast<const uint4*>(Qb + r*32 + s*8);
        *reinterpret_cast<uint4*>(&Ks[r*SMA + s*8]) =
            *reinterpret_cast<const uint4*>(Kb + r*32 + s*8);
        *reinterpret_cast<uint4*>(&Vs[r*SMA + s*8]) =
            *reinterpret_cast<const uint4*>(Vb + r*32 + s*8);
    }
    __syncthreads();

    const int rb = w * 16;

    float sa[8][4];
#pragma unroll
    for (int ni = 0; ni < 8; ++ni)
#pragma unroll
        for (int j = 0; j < 4; ++j) sa[ni][j] = 0.0f;
#pragma unroll
    for (int ks = 0; ks < 2; ++ks) {
        uint32_t a0, a1, a2, a3;
        ldsm_x4(a0, a1, a2, a3, sptr(&Qs[(rb + mrow)*SMA + ks*16 + mcol]));
#pragma unroll
        for (int nb2 = 0; nb2 < 4; ++nb2) {
            uint32_t b0, b1, b2, b3;
            ldsm_x4(b0, b1, b2, b3, sptr(&Ks[(nb2*16 + mrow)*SMA + ks*16 + mcol]));
            mma16816(sa[2*nb2],   a0, a1, a2, a3, b0, b2);
            mma16816(sa[2*nb2+1], a0, a1, a2, a3, b1, b3);
        }
    }

    const int r1 = rb + g, r2 = r1 + 8;
    const float* bm = g_bmask + ((size_t)((win & 63)*8 + head))*4096;
    float mx1 = -1e30f, mx2 = -1e30f;
#pragma unroll
    for (int ni = 0; ni < 8; ++ni) {
        int c = ni*8 + tg*2;
        float2 bv1 = *reinterpret_cast<const float2*>(&bm[r1*64 + c]);
        float2 bv2 = *reinterpret_cast<const float2*>(&bm[r2*64 + c]);
        sa[ni][0] += bv1.x; sa[ni][1] += bv1.y;
        sa[ni][2] += bv2.x; sa[ni][3] += bv2.y;
        mx1 = fmaxf(mx1, fmaxf(sa[ni][0], sa[ni][1]));
        mx2 = fmaxf(mx2, fmaxf(sa[ni][2], sa[ni][3]));
    }
    mx1 = fmaxf(mx1, __shfl_xor_sync(0xffffffffu, mx1, 1));
    mx1 = fmaxf(mx1, __shfl_xor_sync(0xffffffffu, mx1, 2));
    mx2 = fmaxf(mx2, __shfl_xor_sync(0xffffffffu, mx2, 1));
    mx2 = fmaxf(mx2, __shfl_xor_sync(0xffffffffu, mx2, 2));
    float s1 = 0.0f, s2 = 0.0f;
#pragma unroll
    for (int ni = 0; ni < 8; ++ni) {
        sa[ni][0] = __expf(sa[ni][0] - mx1); s1 += sa[ni][0];
        sa[ni][1] = __expf(sa[ni][1] - mx1); s1 += sa[ni][1];
        sa[ni][2] = __expf(sa[ni][2] - mx2); s2 += sa[ni][2];
        sa[ni][3] = __expf(sa[ni][3] - mx2); s2 += sa[ni][3];
    }
    s1 += __shfl_xor_sync(0xffffffffu, s1, 1);
    s1 += __shfl_xor_sync(0xffffffffu, s1, 2);
    s2 += __shfl_xor_sync(0xffffffffu, s2, 1);
    s2 += __shfl_xor_sync(0xffffffffu, s2, 2);
    const float inv1 = 1.0f / s1, inv2 = 1.0f / s2;

    // O = P @ V : V loaded via ldmatrix.trans from row-major [tok][d]
    float oa[4][4];
#pragma unroll
    for (int ni = 0; ni < 4; ++ni)
#pragma unroll
        for (int j = 0; j < 4; ++j) oa[ni][j] = 0.0f;
#pragma unroll
    for (int kc = 0; kc < 4; ++kc) {
        uint32_t a0 = pk2(sa[2*kc][0],   sa[2*kc][1]);
        uint32_t a1 = pk2(sa[2*kc][2],   sa[2*kc][3]);
        uint32_t a2 = pk2(sa[2*kc+1][0], sa[2*kc+1][1]);
        uint32_t a3 = pk2(sa[2*kc+1][2], sa[2*kc+1][3]);
#pragma unroll
        for (int nb2 = 0; nb2 < 2; ++nb2) {
            uint32_t r0f, r1f, r2f, r3f;
            ldsm_x4_trans(r0f, r1f, r2f, r3f,
                          sptr(&Vs[(kc*16 + mrow)*SMA + nb2*16 + mcol]));
            // trans tiles: r0=(d0-7,k0-7) r1=(d0-7,k8-15) r2=(d8-15,k0-7) r3=(d8-15,k8-15)
            mma16816(oa[2*nb2],   a0, a1, a2, a3, r0f, r1f);
            mma16816(oa[2*nb2+1], a0, a1, a2, a3, r2f, r3f);
        }
    }
    bf16* Op = g_O + (size_t)win*64*256 + head*32;
#pragma unroll
    for (int ni = 0; ni < 4; ++ni) {
        int d = ni*8 + tg*2;
        *reinterpret_cast<__nv_bfloat162*>(&Op[(size_t)r1*256 + d]) =
            __floats2bfloat162_rn(oa[ni][0]*inv1, oa[ni][1]*inv1);
        *reinterpret_cast<__nv_bfloat162*>(&Op[(size_t)r2*256 + d]) =
            __floats2bfloat162_rn(oa[ni][2]*inv2, oa[ni][3]*inv2);
    }
}

// ---------------------------------------------------------------------------
extern "C" void kernel_launch(void* const* d_in, const int* in_sizes, int n_in,
                              void* d_out, int out_size)
{
    const float* x      = (const float*)d_in[0];
    const float* ln1_g  = (const float*)d_in[1];
    const float* ln1_b  = (const float*)d_in[2];
    const float* wq     = (const float*)d_in[3];
    const float* bq     = (const float*)d_in[4];
    const float* wk     = (const float*)d_in[5];
    const float* bk     = (const float*)d_in[6];
    const float* wv     = (const float*)d_in[7];
    const float* bv     = (const float*)d_in[8];
    const float* wp     = (const float*)d_in[9];
    const float* bp     = (const float*)d_in[10];
    const float* relb   = (const float*)d_in[11];
    const float* ln2_g  = (const float*)d_in[12];
    const float* ln2_b  = (const float*)d_in[13];
    const float* w1     = (const float*)d_in[14];
    const float* b1     = (const float*)d_in[15];
    const float* w2     = (const float*)d_in[16];
    const float* b2     = (const float*)d_in[17];
    const int*   posi   = (const int*)d_in[18];
    const float* amask  = (const float*)d_in[19];
    float* out = (float*)d_out;

    static bool attr_done = false;
    if (!attr_done) {
        cudaFuncSetAttribute(gemm_kernel,
                             cudaFuncAttributeMaxDynamicSharedMemorySize, GSMEM);
        cudaFuncSetAttribute(proj_ln2_kernel,
                             cudaFuncAttributeMaxDynamicSharedMemorySize, PSMEM);
        attr_done = true;
    }

    const int prep_elems = 196608 + 65536 + 262144 + 262144 + 768 + NWIN*HEADS*4096;
    prep_kernel<<<(prep_elems + 255)/256, 256>>>(wq, wk, wv, wp, w1, w2,
                                                 bq, bk, bv, relb, posi, amask);
    ln1_kernel<<<ROWS/8, 256>>>(x, ln1_g, ln1_b);
    gemm_kernel<<<dim3(6, ROWS/128), 256, GSMEM>>>(0, nullptr, nullptr, nullptr); // QKV
    attn_kernel<<<dim3(HEADS, NWTOT), 128>>>();
    proj_ln2_kernel<<<dim3(1, ROWS/128), 512, PSMEM>>>(bp, x, ln2_g, ln2_b);      // proj+res+LN2
    gemm_kernel<<<dim3(8, ROWS/128), 256, GSMEM>>>(2, b1, nullptr, nullptr);      // mlp1+gelu
    gemm_kernel<<<dim3(2, ROWS/128), 256, GSMEM>>>(3, b2, nullptr, out);          // mlp2+res
}